// round 3
// baseline (speedup 1.0000x reference)
#include <cuda_runtime.h>
#include <cooperative_groups.h>
#include <math.h>

namespace cg = cooperative_groups;

#define BATCH 256
#define SEQT  512
#define EMBD  300
#define HID   150
#define G4    600   // 4*HID
#define RPC   300   // gate rows per CTA (cluster of 2)
#define WS    156   // padded Whh row stride (floats) - conflict-free for float4
#define HS    152   // padded h stride (floats), cols 150..151 stay zero

// ---------------- scratch (static device globals; no allocation) ----------------
__device__ float g_e [(size_t)BATCH*SEQT*EMBD];   // embedding output
__device__ float g_xp[(size_t)BATCH*SEQT*G4];     // x-projection buffer
__device__ float g_sa[(size_t)BATCH*SEQT*HID];    // seq ping
__device__ float g_sb[(size_t)BATCH*SEQT*HID];    // seq pong
__device__ float g_hn[BATCH*HID];                 // final hidden state

// ---------------- embedding gather ----------------
// NOTE: x is int32 on device (JAX default x64-disabled downcasts jnp.int64).
__global__ void embed_k(const int* __restrict__ x, const float* __restrict__ emb) {
    int idx = blockIdx.x * blockDim.x + threadIdx.x;
    const int total = BATCH * SEQT * (EMBD / 4);
    if (idx >= total) return;
    int bt = idx / (EMBD / 4);
    int d4 = (idx - bt * (EMBD / 4)) * 4;
    int row = x[bt];
    const float4 v = *(const float4*)(emb + (size_t)row * EMBD + d4);
    *(float4*)(g_e + (size_t)bt * EMBD + d4) = v;
}

// ---------------- x-projection GEMM: C[M,600] = A[M,K] @ W[600,K]^T + b1 + b2 ----------------
__global__ void gemm_xproj(const float* __restrict__ A, int K,
                           const float* __restrict__ W,
                           const float* __restrict__ b1,
                           const float* __restrict__ b2,
                           float* __restrict__ C) {
    __shared__ float As[16][68];   // [k][m], stride 68 keeps float4 rows 16B aligned
    __shared__ float Bs[16][68];   // [k][n]
    const int tid = threadIdx.x;
    const int m0 = blockIdx.x * 64, n0 = blockIdx.y * 64;
    const int tx = tid & 15, ty = tid >> 4;
    const int lr = tid >> 2, lc = (tid & 3) * 4;

    float acc[4][4];
#pragma unroll
    for (int i = 0; i < 4; i++)
#pragma unroll
        for (int j = 0; j < 4; j++) acc[i][j] = 0.f;

    const float* Arow = A + (size_t)(m0 + lr) * K;
    const int n = n0 + lr;
    const float* Wrow = W + (size_t)n * K;

    for (int k0 = 0; k0 < K; k0 += 16) {
#pragma unroll
        for (int i = 0; i < 4; i++) {
            int k = k0 + lc + i;
            As[lc + i][lr] = (k < K) ? Arow[k] : 0.f;
            Bs[lc + i][lr] = (n < G4 && k < K) ? Wrow[k] : 0.f;
        }
        __syncthreads();
#pragma unroll
        for (int kk = 0; kk < 16; kk++) {
            float4 a = *(const float4*)&As[kk][ty * 4];
            float4 b = *(const float4*)&Bs[kk][tx * 4];
            float av[4] = {a.x, a.y, a.z, a.w};
            float bv[4] = {b.x, b.y, b.z, b.w};
#pragma unroll
            for (int i = 0; i < 4; i++)
#pragma unroll
                for (int j = 0; j < 4; j++)
                    acc[i][j] = fmaf(av[i], bv[j], acc[i][j]);
        }
        __syncthreads();
    }
#pragma unroll
    for (int i = 0; i < 4; i++) {
        float* Crow = C + (size_t)(m0 + ty * 4 + i) * G4;
#pragma unroll
        for (int j = 0; j < 4; j++) {
            int nn = n0 + tx * 4 + j;
            if (nn < G4) Crow[nn] = acc[i][j] + b1[nn] + b2[nn];
        }
    }
}

// ---------------- persistent LSTM layer: 2-CTA cluster per 4 batch elements ----------------
// CTA rank r owns hidden slice [75r, 75r+75): gate rows {g*150 + 75r + j}.
// Whole Whh slice (300x150 fp32) lives in smem; h exchanged via DSMEM each step.
__global__ void __cluster_dims__(2, 1, 1) lstm_k(
    const float* __restrict__ xp, const float* __restrict__ Whh,
    const int* __restrict__ lengths,
    float* __restrict__ seq_out, float* __restrict__ hn_out)
{
    extern __shared__ float sm[];
    float* Wsh   = sm;                 // RPC*WS
    float* h_s   = Wsh + RPC * WS;     // 4*HS   (full h, both halves)
    float* c_s   = h_s + 4 * HS;       // 4*76   (local half of c)
    float* act_s = c_s + 4 * 76;       // 16*76  (nb,gate,j)

    cg::cluster_group cluster = cg::this_cluster();
    const int rank = cluster.block_rank();
    const int tid  = threadIdx.x;
    const int b0   = (blockIdx.x >> 1) * 4;
    float* peer_h = (float*)cluster.map_shared_rank((void*)h_s, rank ^ 1);

    // load Whh slice (rows reindexed to local order), zero pads / state
    for (int idx = tid; idx < RPC * 150; idx += blockDim.x) {
        int r = idx / 150, k = idx - r * 150;
        int gate = r / 75, j = r - gate * 75;
        Wsh[r * WS + k] = Whh[(size_t)(gate * 150 + rank * 75 + j) * 150 + k];
    }
    for (int idx = tid; idx < RPC * (WS - 150); idx += blockDim.x) {
        int r = idx / (WS - 150), k = 150 + idx % (WS - 150);
        Wsh[r * WS + k] = 0.f;
    }
    for (int idx = tid; idx < 4 * HS; idx += blockDim.x) h_s[idx] = 0.f;
    for (int idx = tid; idx < 4 * 76; idx += blockDim.x) c_s[idx] = 0.f;

    const bool active = tid < 600;
    const int p = active ? tid / 300 : 0;       // p: handles nb {2p, 2p+1}
    const int r = active ? tid - p * 300 : 0;   // local gate row 0..299
    const int gate = r / 75, j = r - gate * 75;
    const int grow = gate * 150 + rank * 75 + j;
    const float* wrow = Wsh + r * WS;
    const size_t xb0 = ((size_t)(b0 + 2 * p)     * SEQT) * G4 + grow;
    const size_t xb1 = ((size_t)(b0 + 2 * p + 1) * SEQT) * G4 + grow;

    int mylen = 0, unb = 0, uj = 0;
    if (tid < 300) {
        unb = tid / 75; uj = tid - unb * 75;
        mylen = lengths[b0 + unb];
    }

    cluster.sync();

    for (int t = 0; t < SEQT; t++) {
        if (active) {
            float xg0 = xp[xb0 + (size_t)t * G4];
            float xg1 = xp[xb1 + (size_t)t * G4];
            float acc0 = 0.f, acc1 = 0.f;
            const float* hA = h_s + (2 * p) * HS;
            const float* hB = hA + HS;
#pragma unroll
            for (int k = 0; k < HS; k += 4) {
                float4 w = *(const float4*)(wrow + k);
                float4 a = *(const float4*)(hA + k);
                float4 b = *(const float4*)(hB + k);
                acc0 = fmaf(w.x, a.x, acc0); acc0 = fmaf(w.y, a.y, acc0);
                acc0 = fmaf(w.z, a.z, acc0); acc0 = fmaf(w.w, a.w, acc0);
                acc1 = fmaf(w.x, b.x, acc1); acc1 = fmaf(w.y, b.y, acc1);
                acc1 = fmaf(w.z, b.z, acc1); acc1 = fmaf(w.w, b.w, acc1);
            }
            float pre0 = acc0 + xg0, pre1 = acc1 + xg1;
            float v0, v1;
            if (gate == 2) { v0 = tanhf(pre0); v1 = tanhf(pre1); }
            else {
                v0 = 1.f / (1.f + __expf(-pre0));
                v1 = 1.f / (1.f + __expf(-pre1));
            }
            act_s[((2 * p) * 4 + gate) * 76 + j]     = v0;
            act_s[((2 * p + 1) * 4 + gate) * 76 + j] = v1;
        }
        __syncthreads();
        if (tid < 300) {
            float gi = act_s[(unb * 4 + 0) * 76 + uj];
            float gf = act_s[(unb * 4 + 1) * 76 + uj];
            float gg = act_s[(unb * 4 + 2) * 76 + uj];
            float go = act_s[(unb * 4 + 3) * 76 + uj];
            float c  = c_s[unb * 76 + uj];
            float cn = fmaf(gf, c, gi * gg);
            float hv = go * tanhf(cn);
            bool msk = t < mylen;
            seq_out[((size_t)(b0 + unb) * SEQT + t) * HID + rank * 75 + uj] = msk ? hv : 0.f;
            if (msk) {
                c_s[unb * 76 + uj] = cn;
                h_s[unb * HS + rank * 75 + uj]    = hv;
                peer_h[unb * HS + rank * 75 + uj] = hv;  // DSMEM: keep peer's copy coherent
            }
        }
        cluster.sync();  // orders local + DSMEM h writes before next step's reads
    }

    if (tid < 300)
        hn_out[(b0 + unb) * HID + rank * 75 + uj] = h_s[unb * HS + rank * 75 + uj];
}

// ---------------- FC head: out[b] = fc2 . relu(fc1 @ hn[b] + b1) + b2 ----------------
__global__ void fc_k(const float* __restrict__ hn, const float* __restrict__ w1,
                     const float* __restrict__ b1v, const float* __restrict__ w2,
                     const float* __restrict__ b2v, float* __restrict__ out) {
    __shared__ float red[256];
    int b = blockIdx.x, tid = threadIdx.x;
    float part = 0.f;
    if (tid < HID) {
        float acc = 0.f;
        const float* hr = hn + b * HID;
        const float* wr = w1 + tid * HID;
        for (int k = 0; k < HID; k++) acc = fmaf(wr[k], hr[k], acc);
        float z = fmaxf(acc + b1v[tid], 0.f);
        part = z * w2[tid];
    }
    red[tid] = part;
    __syncthreads();
    for (int s = 128; s > 0; s >>= 1) {
        if (tid < s) red[tid] += red[tid + s];
        __syncthreads();
    }
    if (tid == 0) out[b] = red[0] + b2v[0];
}

// ---------------- launch ----------------
extern "C" void kernel_launch(void* const* d_in, const int* in_sizes, int n_in,
                              void* d_out, int out_size) {
    const int* x   = (const int*)d_in[0];
    const int* len = (const int*)d_in[1];
    const float* emb = (const float*)d_in[2];
    const float *Wih[4], *Whh[4], *bih[4], *bhh[4];
    for (int l = 0; l < 4; l++) {
        Wih[l] = (const float*)d_in[3 + 4 * l];
        Whh[l] = (const float*)d_in[4 + 4 * l];
        bih[l] = (const float*)d_in[5 + 4 * l];
        bhh[l] = (const float*)d_in[6 + 4 * l];
    }
    const float* fc1w = (const float*)d_in[19];
    const float* fc1b = (const float*)d_in[20];
    const float* fc2w = (const float*)d_in[21];
    const float* fc2b = (const float*)d_in[22];
    float* out = (float*)d_out;

    float *pe, *pxp, *psa, *psb, *phn;
    cudaGetSymbolAddress((void**)&pe,  g_e);
    cudaGetSymbolAddress((void**)&pxp, g_xp);
    cudaGetSymbolAddress((void**)&psa, g_sa);
    cudaGetSymbolAddress((void**)&psb, g_sb);
    cudaGetSymbolAddress((void**)&phn, g_hn);

    const int SMEM = (RPC * WS + 4 * HS + 4 * 76 + 16 * 76) * 4;  // ~195.7 KB
    cudaFuncSetAttribute(lstm_k, cudaFuncAttributeMaxDynamicSharedMemorySize, SMEM);

    embed_k<<<38400, 256>>>(x, emb);

    dim3 gg(2048, 10);
    gemm_xproj<<<gg, 256>>>(pe,  EMBD, Wih[0], bih[0], bhh[0], pxp);
    lstm_k<<<128, 608, SMEM>>>(pxp, Whh[0], len, psa, phn);

    gemm_xproj<<<gg, 256>>>(psa, HID,  Wih[1], bih[1], bhh[1], pxp);
    lstm_k<<<128, 608, SMEM>>>(pxp, Whh[1], len, psb, phn);

    gemm_xproj<<<gg, 256>>>(psb, HID,  Wih[2], bih[2], bhh[2], pxp);
    lstm_k<<<128, 608, SMEM>>>(pxp, Whh[2], len, psa, phn);

    gemm_xproj<<<gg, 256>>>(psa, HID,  Wih[3], bih[3], bhh[3], pxp);
    lstm_k<<<128, 608, SMEM>>>(pxp, Whh[3], len, psb, phn);

    fc_k<<<256, 256>>>(phn, fc1w, fc1b, fc2w, fc2b, out);
}

// round 4
// speedup vs baseline: 1.3471x; 1.3471x over previous
#include <cuda_runtime.h>
#include <math.h>

#define BATCH 256
#define SEQT  512
#define EMBD  300
#define HID   150
#define G4    600   // 4*HID
#define SMW   92    // Whh cols kept in smem (stride 92 words: 92%32=28 -> conflict-free float4)
#define NRW   58    // Whh cols kept in registers (92+58=150)
#define HS    152   // padded h/c stride

// ---------------- scratch (static device globals; no allocation) ----------------
__device__ float g_e [(size_t)BATCH*SEQT*EMBD];   // embedding output
__device__ float g_xp[(size_t)BATCH*SEQT*G4];     // x-projection buffer
__device__ float g_sa[(size_t)BATCH*SEQT*HID];    // seq ping
__device__ float g_sb[(size_t)BATCH*SEQT*HID];    // seq pong
__device__ float g_hn[BATCH*HID];                 // final hidden state

// ---------------- embedding gather (x is int32 on device) ----------------
__global__ void embed_k(const int* __restrict__ x, const float* __restrict__ emb) {
    int idx = blockIdx.x * blockDim.x + threadIdx.x;
    const int total = BATCH * SEQT * (EMBD / 4);
    if (idx >= total) return;
    int bt = idx / (EMBD / 4);
    int d4 = (idx - bt * (EMBD / 4)) * 4;
    int row = x[bt];
    const float4 v = *(const float4*)(emb + (size_t)row * EMBD + d4);
    *(float4*)(g_e + (size_t)bt * EMBD + d4) = v;
}

// ---------------- x-projection GEMM: C[M,600] = A[M,K] @ W[600,K]^T + b1 + b2 ----------------
// 128x128 tile, 256 threads, 8x8 micro-tile laid out as 2x2 blocks of 4x4 at offsets {0,64}.
__global__ void __launch_bounds__(256) gemm_xproj(
    const float* __restrict__ A, int K,
    const float* __restrict__ W,
    const float* __restrict__ b1,
    const float* __restrict__ b2,
    float* __restrict__ C) {
    __shared__ float As[16][132];
    __shared__ float Bs[16][132];
    const int tid = threadIdx.x;
    const int m0 = blockIdx.x * 128, n0 = blockIdx.y * 128;
    const int tx = tid & 15, ty = tid >> 4;
    const int lr = tid >> 1, lk = (tid & 1) * 8;

    float acc[8][8];
#pragma unroll
    for (int i = 0; i < 8; i++)
#pragma unroll
        for (int j = 0; j < 8; j++) acc[i][j] = 0.f;

    const float* Ap = A + (size_t)(m0 + lr) * K;
    const int nrow = n0 + lr;
    const float* Wp = W + (size_t)nrow * K;
    const bool wok = nrow < G4;
    const int nt = (K + 15) / 16;

    for (int kt = 0; kt < nt; kt++) {
        const int k0 = kt * 16;
#pragma unroll
        for (int c = 0; c < 4; c++) {
            int k = k0 + lk + 2 * c;
            float2 av = (k < K) ? *(const float2*)(Ap + k) : make_float2(0.f, 0.f);
            float2 wv = (wok && k < K) ? *(const float2*)(Wp + k) : make_float2(0.f, 0.f);
            As[lk + 2 * c][lr]     = av.x;
            As[lk + 2 * c + 1][lr] = av.y;
            Bs[lk + 2 * c][lr]     = wv.x;
            Bs[lk + 2 * c + 1][lr] = wv.y;
        }
        __syncthreads();
#pragma unroll
        for (int kk = 0; kk < 16; kk++) {
            float4 al = *(const float4*)&As[kk][ty * 4];
            float4 ah = *(const float4*)&As[kk][64 + ty * 4];
            float4 bl = *(const float4*)&Bs[kk][tx * 4];
            float4 bh = *(const float4*)&Bs[kk][64 + tx * 4];
            float av[8] = {al.x, al.y, al.z, al.w, ah.x, ah.y, ah.z, ah.w};
            float bv[8] = {bl.x, bl.y, bl.z, bl.w, bh.x, bh.y, bh.z, bh.w};
#pragma unroll
            for (int i = 0; i < 8; i++)
#pragma unroll
                for (int j = 0; j < 8; j++)
                    acc[i][j] = fmaf(av[i], bv[j], acc[i][j]);
        }
        __syncthreads();
    }
#pragma unroll
    for (int i = 0; i < 8; i++) {
        int m = m0 + ((i < 4) ? ty * 4 + i : 64 + ty * 4 + (i - 4));
        float* Cr = C + (size_t)m * G4;
#pragma unroll
        for (int j = 0; j < 8; j++) {
            int nn = n0 + ((j < 4) ? tx * 4 + j : 64 + tx * 4 + (j - 4));
            if (nn < G4) Cr[nn] = acc[i][j] + b1[nn] + b2[nn];
        }
    }
}

// ---------------- LSTM layer: ONE CTA per 2 batch elements (no cluster) ----------------
// Thread r<600 owns gate row r for both batches; W row split: cols [0,92) smem, [92,150) regs.
__global__ void __launch_bounds__(608, 1) lstm_k(
    const float* __restrict__ xp, const float* __restrict__ Whh,
    const int* __restrict__ lengths,
    float* __restrict__ seq_out, float* __restrict__ hn_out)
{
    extern __shared__ float sm[];
    float* Wsh = sm;                    // 600*92
    float* h_s = Wsh + 600 * SMW;       // 2*HS
    float* c_s = h_s + 2 * HS;          // 2*HS
    float* act = c_s + 2 * HS;          // 8*HS : [b][gate][j]

    const int tid = threadIdx.x;
    const int b0  = blockIdx.x * 2;

    // load Whh smem part (cols 0..91 of each row), coalesced-ish grid-stride
    for (int idx = tid; idx < 600 * SMW; idx += 608) {
        int r = idx / SMW, k = idx - r * SMW;
        Wsh[r * SMW + k] = Whh[(size_t)r * 150 + k];
    }
    for (int idx = tid; idx < 2 * HS; idx += 608) { h_s[idx] = 0.f; c_s[idx] = 0.f; }

    // register part: cols 92..149 of this thread's row
    float wr[NRW];
    const int r = (tid < 600) ? tid : 0;
#pragma unroll
    for (int i = 0; i < NRW; i++)
        wr[i] = (tid < 600) ? Whh[(size_t)r * 150 + SMW + i] : 0.f;

    const int gate = r / 150;
    const float* wp = Wsh + r * SMW;
    const size_t xbA = ((size_t)b0 * SEQT) * G4 + r;
    const size_t xbB = ((size_t)(b0 + 1) * SEQT) * G4 + r;

    int ub = 0, uj = 0, mylen = 0;
    if (tid < 300) {
        ub = tid / 150; uj = tid - ub * 150;
        mylen = lengths[b0 + ub];
    }

    __syncthreads();

    for (int t = 0; t < SEQT; t++) {
        if (tid < 600) {
            float xgA = xp[xbA + (size_t)t * G4];
            float xgB = xp[xbB + (size_t)t * G4];
            float accA = 0.f, accB = 0.f;
            const float* hA = h_s;
            const float* hB = h_s + HS;
#pragma unroll
            for (int k = 0; k < SMW; k += 4) {
                float4 w = *(const float4*)(wp + k);
                float4 a = *(const float4*)(hA + k);
                float4 b = *(const float4*)(hB + k);
                accA = fmaf(w.x, a.x, accA); accA = fmaf(w.y, a.y, accA);
                accA = fmaf(w.z, a.z, accA); accA = fmaf(w.w, a.w, accA);
                accB = fmaf(w.x, b.x, accB); accB = fmaf(w.y, b.y, accB);
                accB = fmaf(w.z, b.z, accB); accB = fmaf(w.w, b.w, accB);
            }
#pragma unroll
            for (int c = 0; c < 14; c++) {   // cols 92..147 from registers
                float4 a = *(const float4*)(hA + SMW + 4 * c);
                float4 b = *(const float4*)(hB + SMW + 4 * c);
                accA = fmaf(wr[4 * c], a.x, accA); accA = fmaf(wr[4 * c + 1], a.y, accA);
                accA = fmaf(wr[4 * c + 2], a.z, accA); accA = fmaf(wr[4 * c + 3], a.w, accA);
                accB = fmaf(wr[4 * c], b.x, accB); accB = fmaf(wr[4 * c + 1], b.y, accB);
                accB = fmaf(wr[4 * c + 2], b.z, accB); accB = fmaf(wr[4 * c + 3], b.w, accB);
            }
            {   // cols 148,149
                float2 a = *(const float2*)(hA + 148);
                float2 b = *(const float2*)(hB + 148);
                accA = fmaf(wr[56], a.x, accA); accA = fmaf(wr[57], a.y, accA);
                accB = fmaf(wr[56], b.x, accB); accB = fmaf(wr[57], b.y, accB);
            }
            float preA = accA + xgA, preB = accB + xgB;
            float vA, vB;
            if (gate == 2) { vA = tanhf(preA); vB = tanhf(preB); }
            else {
                vA = 1.f / (1.f + __expf(-preA));
                vB = 1.f / (1.f + __expf(-preB));
            }
            act[(0 * 4 + gate) * HS + (r - gate * 150)] = vA;   // wait: index by j
            act[(1 * 4 + gate) * HS + (r - gate * 150)] = vB;
        }
        __syncthreads();
        if (tid < 300) {
            float gi = act[(ub * 4 + 0) * HS + uj];
            float gf = act[(ub * 4 + 1) * HS + uj];
            float gg = act[(ub * 4 + 2) * HS + uj];
            float go = act[(ub * 4 + 3) * HS + uj];
            float c  = c_s[ub * HS + uj];
            float cn = fmaf(gf, c, gi * gg);
            float hv = go * tanhf(cn);
            bool msk = t < mylen;
            seq_out[((size_t)(b0 + ub) * SEQT + t) * HID + uj] = msk ? hv : 0.f;
            if (msk) {
                c_s[ub * HS + uj] = cn;
                h_s[ub * HS + uj] = hv;
            }
        }
        __syncthreads();
    }

    if (tid < 300)
        hn_out[(b0 + ub) * HID + uj] = h_s[ub * HS + uj];
}

// ---------------- FC head ----------------
__global__ void fc_k(const float* __restrict__ hn, const float* __restrict__ w1,
                     const float* __restrict__ b1v, const float* __restrict__ w2,
                     const float* __restrict__ b2v, float* __restrict__ out) {
    __shared__ float red[256];
    int b = blockIdx.x, tid = threadIdx.x;
    float part = 0.f;
    if (tid < HID) {
        float acc = 0.f;
        const float* hr = hn + b * HID;
        const float* wrw = w1 + tid * HID;
        for (int k = 0; k < HID; k++) acc = fmaf(wrw[k], hr[k], acc);
        float z = fmaxf(acc + b1v[tid], 0.f);
        part = z * w2[tid];
    }
    red[tid] = part;
    __syncthreads();
    for (int s = 128; s > 0; s >>= 1) {
        if (tid < s) red[tid] += red[tid + s];
        __syncthreads();
    }
    if (tid == 0) out[b] = red[0] + b2v[0];
}

// ---------------- launch ----------------
extern "C" void kernel_launch(void* const* d_in, const int* in_sizes, int n_in,
                              void* d_out, int out_size) {
    const int* x   = (const int*)d_in[0];
    const int* len = (const int*)d_in[1];
    const float* emb = (const float*)d_in[2];
    const float *Wih[4], *Whh[4], *bih[4], *bhh[4];
    for (int l = 0; l < 4; l++) {
        Wih[l] = (const float*)d_in[3 + 4 * l];
        Whh[l] = (const float*)d_in[4 + 4 * l];
        bih[l] = (const float*)d_in[5 + 4 * l];
        bhh[l] = (const float*)d_in[6 + 4 * l];
    }
    const float* fc1w = (const float*)d_in[19];
    const float* fc1b = (const float*)d_in[20];
    const float* fc2w = (const float*)d_in[21];
    const float* fc2b = (const float*)d_in[22];
    float* out = (float*)d_out;

    float *pe, *pxp, *psa, *psb, *phn;
    cudaGetSymbolAddress((void**)&pe,  g_e);
    cudaGetSymbolAddress((void**)&pxp, g_xp);
    cudaGetSymbolAddress((void**)&psa, g_sa);
    cudaGetSymbolAddress((void**)&psb, g_sb);
    cudaGetSymbolAddress((void**)&phn, g_hn);

    const int SMEM = (600 * SMW + 2 * HS + 2 * HS + 8 * HS) * 4;  // 228096 B
    cudaFuncSetAttribute(lstm_k, cudaFuncAttributeMaxDynamicSharedMemorySize, SMEM);

    embed_k<<<38400, 256>>>(x, emb);

    dim3 gg(1024, 5);
    gemm_xproj<<<gg, 256>>>(pe,  EMBD, Wih[0], bih[0], bhh[0], pxp);
    lstm_k<<<128, 608, SMEM>>>(pxp, Whh[0], len, psa, phn);

    gemm_xproj<<<gg, 256>>>(psa, HID,  Wih[1], bih[1], bhh[1], pxp);
    lstm_k<<<128, 608, SMEM>>>(pxp, Whh[1], len, psb, phn);

    gemm_xproj<<<gg, 256>>>(psb, HID,  Wih[2], bih[2], bhh[2], pxp);
    lstm_k<<<128, 608, SMEM>>>(pxp, Whh[2], len, psa, phn);

    gemm_xproj<<<gg, 256>>>(psa, HID,  Wih[3], bih[3], bhh[3], pxp);
    lstm_k<<<128, 608, SMEM>>>(pxp, Whh[3], len, psb, phn);

    fc_k<<<256, 256>>>(phn, fc1w, fc1b, fc2w, fc2b, out);
}

// round 5
// speedup vs baseline: 1.4014x; 1.0403x over previous
#include <cuda_runtime.h>
#include <math.h>

typedef unsigned long long ull;

#define BATCH 256
#define SEQT  512
#define EMBD  300
#define HID   150
#define G4    600   // 4*HID
#define SMW   84    // Whh cols in smem (84 % 32 = 20 -> conflict-free float4 rows)
#define NRW   66    // Whh cols in registers (84+66=150) = 33 u64
#define HS    152   // padded h/c stride (608B: 16B-aligned)

#define FMA2(d, a, b) asm("fma.rn.f32x2 %0, %1, %2, %3;" : "=l"(d) : "l"(a), "l"(b), "l"(d))

__device__ __forceinline__ float sig_f(float x)  { return __fdividef(1.f, 1.f + __expf(-x)); }
__device__ __forceinline__ float tanh_f(float x) { return 1.f - __fdividef(2.f, __expf(2.f * x) + 1.f); }

// ---------------- scratch (static device globals; no allocation) ----------------
__device__ float g_e [(size_t)BATCH*SEQT*EMBD];
__device__ float g_xp[(size_t)BATCH*SEQT*G4];
__device__ float g_sa[(size_t)BATCH*SEQT*HID];
__device__ float g_sb[(size_t)BATCH*SEQT*HID];
__device__ float g_hn[BATCH*HID];

// ---------------- embedding gather (x is int32 on device) ----------------
__global__ void embed_k(const int* __restrict__ x, const float* __restrict__ emb) {
    int idx = blockIdx.x * blockDim.x + threadIdx.x;
    const int total = BATCH * SEQT * (EMBD / 4);
    if (idx >= total) return;
    int bt = idx / (EMBD / 4);
    int d4 = (idx - bt * (EMBD / 4)) * 4;
    int row = x[bt];
    const float4 v = *(const float4*)(emb + (size_t)row * EMBD + d4);
    *(float4*)(g_e + (size_t)bt * EMBD + d4) = v;
}

// ---------------- x-projection GEMM: C[M,600] = A[M,K] @ W[600,K]^T + b1 + b2 ----------------
// 128x128 tile, 256 threads, 8x8 micro-tile; f32x2 packed along N (b pairs free via u64 loads).
__global__ void __launch_bounds__(256) gemm_xproj(
    const float* __restrict__ A, int K,
    const float* __restrict__ W,
    const float* __restrict__ b1,
    const float* __restrict__ b2,
    float* __restrict__ C) {
    __shared__ float As[16][132];
    __shared__ float Bs[16][132];
    const int tid = threadIdx.x;
    const int m0 = blockIdx.x * 128, n0 = blockIdx.y * 128;
    const int tx = tid & 15, ty = tid >> 4;
    const int lr = tid >> 1, lk = (tid & 1) * 8;

    ull acc2[8][4];
#pragma unroll
    for (int i = 0; i < 8; i++)
#pragma unroll
        for (int j = 0; j < 4; j++) acc2[i][j] = 0ull;

    const float* Ap = A + (size_t)(m0 + lr) * K;
    const int nrow = n0 + lr;
    const float* Wp = W + (size_t)nrow * K;
    const bool wok = nrow < G4;
    const int nt = (K + 15) / 16;

    for (int kt = 0; kt < nt; kt++) {
        const int k0 = kt * 16;
#pragma unroll
        for (int c = 0; c < 4; c++) {
            int k = k0 + lk + 2 * c;
            float2 av = (k < K) ? *(const float2*)(Ap + k) : make_float2(0.f, 0.f);
            float2 wv = (wok && k < K) ? *(const float2*)(Wp + k) : make_float2(0.f, 0.f);
            As[lk + 2 * c][lr]     = av.x;
            As[lk + 2 * c + 1][lr] = av.y;
            Bs[lk + 2 * c][lr]     = wv.x;
            Bs[lk + 2 * c + 1][lr] = wv.y;
        }
        __syncthreads();
#pragma unroll
        for (int kk = 0; kk < 16; kk++) {
            float4 al = *(const float4*)&As[kk][ty * 4];
            float4 ah = *(const float4*)&As[kk][64 + ty * 4];
            ulonglong2 bl = *(const ulonglong2*)&Bs[kk][tx * 4];
            ulonglong2 bh = *(const ulonglong2*)&Bs[kk][64 + tx * 4];
            float a_s[8] = {al.x, al.y, al.z, al.w, ah.x, ah.y, ah.z, ah.w};
#pragma unroll
            for (int i = 0; i < 8; i++) {
                float2 t = make_float2(a_s[i], a_s[i]);
                ull ad = *(ull*)&t;
                FMA2(acc2[i][0], ad, bl.x);
                FMA2(acc2[i][1], ad, bl.y);
                FMA2(acc2[i][2], ad, bh.x);
                FMA2(acc2[i][3], ad, bh.y);
            }
        }
        __syncthreads();
    }
#pragma unroll
    for (int i = 0; i < 8; i++) {
        int m = m0 + ((i < 4) ? ty * 4 + i : 64 + ty * 4 + (i - 4));
        float* Cr = C + (size_t)m * G4;
#pragma unroll
        for (int j2 = 0; j2 < 4; j2++) {
            float2 p = *(float2*)&acc2[i][j2];
            int nn = n0 + ((j2 < 2) ? tx * 4 + 2 * j2 : 64 + tx * 4 + 2 * (j2 - 2));
            if (nn < G4)     Cr[nn]     = p.x + b1[nn]     + b2[nn];
            if (nn + 1 < G4) Cr[nn + 1] = p.y + b1[nn + 1] + b2[nn + 1];
        }
    }
}

// ---------------- LSTM layer: ONE CTA per 2 batch elements ----------------
// Thread r<600 owns gate row r for both batches; W row: cols [0,84) smem, [84,150) regs.
// Dot product packed f32x2 along k (pairs {k,k+1} free via ulonglong2 loads).
__global__ void __launch_bounds__(608, 1) lstm_k(
    const float* __restrict__ xp, const float* __restrict__ Whh,
    const int* __restrict__ lengths,
    float* __restrict__ seq_out, float* __restrict__ hn_out)
{
    extern __shared__ float sm[];
    float* Wsh = sm;                    // 600*SMW
    float* h_s = Wsh + 600 * SMW;       // 2*HS
    float* c_s = h_s + 2 * HS;          // 2*HS
    float* act = c_s + 2 * HS;          // 8*HS : [b][gate][j]

    const int tid = threadIdx.x;
    const int b0  = blockIdx.x * 2;

    for (int idx = tid; idx < 600 * SMW; idx += 608) {
        int r = idx / SMW, k = idx - r * SMW;
        Wsh[r * SMW + k] = Whh[(size_t)r * 150 + k];
    }
    for (int idx = tid; idx < 2 * HS; idx += 608) { h_s[idx] = 0.f; c_s[idx] = 0.f; }

    // register part: cols 84..149 as 33 packed u64 pairs
    ull wr2[33];
    const int r = (tid < 600) ? tid : 0;
    const float* wg = Whh + (size_t)r * 150 + SMW;
#pragma unroll
    for (int i = 0; i < 33; i++)
        wr2[i] = (tid < 600) ? *(const ull*)(wg + 2 * i) : 0ull;

    const int gate = r / 150;
    const int jrow = r - gate * 150;
    const float* wp = Wsh + r * SMW;
    const size_t xbA = ((size_t)b0 * SEQT) * G4 + r;
    const size_t xbB = ((size_t)(b0 + 1) * SEQT) * G4 + r;

    int ub = 0, uj = 0, mylen = 0;
    if (tid < 300) {
        ub = tid / 150; uj = tid - ub * 150;
        mylen = lengths[b0 + ub];
    }

    __syncthreads();

    for (int t = 0; t < SEQT; t++) {
        if (tid < 600) {
            float xgA = xp[xbA + (size_t)t * G4];
            float xgB = xp[xbB + (size_t)t * G4];
            ull acc2A = 0ull, acc2B = 0ull;
            const float* hA = h_s;
            const float* hB = h_s + HS;
#pragma unroll
            for (int k = 0; k < SMW; k += 4) {
                ulonglong2 w2 = *(const ulonglong2*)(wp + k);
                ulonglong2 a2 = *(const ulonglong2*)(hA + k);
                ulonglong2 b2 = *(const ulonglong2*)(hB + k);
                FMA2(acc2A, w2.x, a2.x); FMA2(acc2A, w2.y, a2.y);
                FMA2(acc2B, w2.x, b2.x); FMA2(acc2B, w2.y, b2.y);
            }
#pragma unroll
            for (int c = 0; c < 16; c++) {       // cols 84..147 from registers
                ulonglong2 a2 = *(const ulonglong2*)(hA + SMW + 4 * c);
                ulonglong2 b2 = *(const ulonglong2*)(hB + SMW + 4 * c);
                FMA2(acc2A, wr2[2 * c], a2.x); FMA2(acc2A, wr2[2 * c + 1], a2.y);
                FMA2(acc2B, wr2[2 * c], b2.x); FMA2(acc2B, wr2[2 * c + 1], b2.y);
            }
            {                                    // cols 148,149
                ull a1 = *(const ull*)(hA + 148);
                ull b1 = *(const ull*)(hB + 148);
                FMA2(acc2A, wr2[32], a1); FMA2(acc2B, wr2[32], b1);
            }
            float2 fA = *(float2*)&acc2A;
            float2 fB = *(float2*)&acc2B;
            float preA = fA.x + fA.y + xgA;
            float preB = fB.x + fB.y + xgB;
            float vA, vB;
            if (gate == 2) { vA = tanh_f(preA); vB = tanh_f(preB); }
            else           { vA = sig_f(preA);  vB = sig_f(preB);  }
            act[(0 * 4 + gate) * HS + jrow] = vA;
            act[(1 * 4 + gate) * HS + jrow] = vB;
        }
        __syncthreads();
        if (tid < 300) {
            float gi = act[(ub * 4 + 0) * HS + uj];
            float gf = act[(ub * 4 + 1) * HS + uj];
            float gg = act[(ub * 4 + 2) * HS + uj];
            float go = act[(ub * 4 + 3) * HS + uj];
            float c  = c_s[ub * HS + uj];
            float cn = fmaf(gf, c, gi * gg);
            float hv = go * tanh_f(cn);
            bool msk = t < mylen;
            seq_out[((size_t)(b0 + ub) * SEQT + t) * HID + uj] = msk ? hv : 0.f;
            if (msk) {
                c_s[ub * HS + uj] = cn;
                h_s[ub * HS + uj] = hv;
            }
        }
        __syncthreads();
    }

    if (tid < 300)
        hn_out[(b0 + ub) * HID + uj] = h_s[ub * HS + uj];
}

// ---------------- FC head ----------------
__global__ void fc_k(const float* __restrict__ hn, const float* __restrict__ w1,
                     const float* __restrict__ b1v, const float* __restrict__ w2,
                     const float* __restrict__ b2v, float* __restrict__ out) {
    __shared__ float red[256];
    int b = blockIdx.x, tid = threadIdx.x;
    float part = 0.f;
    if (tid < HID) {
        float acc = 0.f;
        const float* hr = hn + b * HID;
        const float* wrw = w1 + tid * HID;
        for (int k = 0; k < HID; k++) acc = fmaf(wrw[k], hr[k], acc);
        float z = fmaxf(acc + b1v[tid], 0.f);
        part = z * w2[tid];
    }
    red[tid] = part;
    __syncthreads();
    for (int s = 128; s > 0; s >>= 1) {
        if (tid < s) red[tid] += red[tid + s];
        __syncthreads();
    }
    if (tid == 0) out[b] = red[0] + b2v[0];
}

// ---------------- launch ----------------
extern "C" void kernel_launch(void* const* d_in, const int* in_sizes, int n_in,
                              void* d_out, int out_size) {
    const int* x   = (const int*)d_in[0];
    const int* len = (const int*)d_in[1];
    const float* emb = (const float*)d_in[2];
    const float *Wih[4], *Whh[4], *bih[4], *bhh[4];
    for (int l = 0; l < 4; l++) {
        Wih[l] = (const float*)d_in[3 + 4 * l];
        Whh[l] = (const float*)d_in[4 + 4 * l];
        bih[l] = (const float*)d_in[5 + 4 * l];
        bhh[l] = (const float*)d_in[6 + 4 * l];
    }
    const float* fc1w = (const float*)d_in[19];
    const float* fc1b = (const float*)d_in[20];
    const float* fc2w = (const float*)d_in[21];
    const float* fc2b = (const float*)d_in[22];
    float* out = (float*)d_out;

    float *pe, *pxp, *psa, *psb, *phn;
    cudaGetSymbolAddress((void**)&pe,  g_e);
    cudaGetSymbolAddress((void**)&pxp, g_xp);
    cudaGetSymbolAddress((void**)&psa, g_sa);
    cudaGetSymbolAddress((void**)&psb, g_sb);
    cudaGetSymbolAddress((void**)&phn, g_hn);

    const int SMEM = (600 * SMW + 2 * HS + 2 * HS + 8 * HS) * 4;  // 208896 B
    cudaFuncSetAttribute(lstm_k, cudaFuncAttributeMaxDynamicSharedMemorySize, SMEM);

    embed_k<<<38400, 256>>>(x, emb);

    dim3 gg(1024, 5);
    gemm_xproj<<<gg, 256>>>(pe,  EMBD, Wih[0], bih[0], bhh[0], pxp);
    lstm_k<<<128, 608, SMEM>>>(pxp, Whh[0], len, psa, phn);

    gemm_xproj<<<gg, 256>>>(psa, HID,  Wih[1], bih[1], bhh[1], pxp);
    lstm_k<<<128, 608, SMEM>>>(pxp, Whh[1], len, psb, phn);

    gemm_xproj<<<gg, 256>>>(psb, HID,  Wih[2], bih[2], bhh[2], pxp);
    lstm_k<<<128, 608, SMEM>>>(pxp, Whh[2], len, psa, phn);

    gemm_xproj<<<gg, 256>>>(psa, HID,  Wih[3], bih[3], bhh[3], pxp);
    lstm_k<<<128, 608, SMEM>>>(pxp, Whh[3], len, psb, phn);

    fc_k<<<256, 256>>>(phn, fc1w, fc1b, fc2w, fc2b, out);
}